// round 14
// baseline (speedup 1.0000x reference)
#include <cuda_runtime.h>
#include <cuda_fp16.h>
#include <cstdint>
#include <cstddef>

// Problem dims (fixed by the dataset)
#define M_DIM 8192
#define N_DIM 4096
#define K_DIM 4096

#define BM 128
#define BN 256
#define BK 64                                  // 64 halves = 128 B per row
#define KT (K_DIM / BK)                        // 64 iterations per tile
#define ROW_BYTES 8192                         // one K row in fp16
#define A_BLK 16384                            // stage A: 128 rows x 128 B
#define B_BLK 32768                            // stage B: 256 rows x 128 B
#define STAGE_BYTES (A_BLK + B_BLK)            // 49152
#define STAGES 4
#define SMEM_CTRL 1024
#define SMEM_TOTAL (SMEM_CTRL + STAGES * STAGE_BYTES)   // 197632

// Scratch (allocation-free rule: __device__ globals)
// NATURAL row-major fp16 with the XOR swizzle applied inside each 128B
// segment: byte(m, kt, g) = m*8192 + kt*128 + ((g ^ (m&7))<<4).
__device__ __half g_Xh[(size_t)M_DIM * K_DIM];   // 64 MB
__device__ __half g_Wh[(size_t)N_DIM * K_DIM];   // 32 MB (W + 2*B@A)

// ---------------------------------------------------------------------------
// helpers
// ---------------------------------------------------------------------------
__device__ __forceinline__ void ldsm4(uint32_t& r0, uint32_t& r1, uint32_t& r2, uint32_t& r3,
                                      uint32_t saddr) {
    asm volatile("ldmatrix.sync.aligned.m8n8.x4.shared.b16 {%0,%1,%2,%3}, [%4];\n"
                 : "=r"(r0), "=r"(r1), "=r"(r2), "=r"(r3) : "r"(saddr));
}

__device__ __forceinline__ void mma_f16(float* d, const uint32_t* a, uint32_t b0, uint32_t b1) {
    asm volatile(
        "mma.sync.aligned.m16n8k16.row.col.f32.f16.f16.f32 "
        "{%0,%1,%2,%3},{%4,%5,%6,%7},{%8,%9},{%0,%1,%2,%3};\n"
        : "+f"(d[0]), "+f"(d[1]), "+f"(d[2]), "+f"(d[3])
        : "r"(a[0]), "r"(a[1]), "r"(a[2]), "r"(a[3]), "r"(b0), "r"(b1));
}

__device__ __forceinline__ void mbar_init(uint32_t mbar, uint32_t count) {
    asm volatile("mbarrier.init.shared.b64 [%0], %1;" :: "r"(mbar), "r"(count) : "memory");
}

__device__ __forceinline__ void mbar_expect_tx(uint32_t mbar, uint32_t bytes) {
    asm volatile("mbarrier.arrive.expect_tx.shared.b64 _, [%0], %1;"
                 :: "r"(mbar), "r"(bytes) : "memory");
}

__device__ __forceinline__ void mbar_arrive(uint32_t mbar) {
    asm volatile("mbarrier.arrive.shared.b64 _, [%0];" :: "r"(mbar) : "memory");
}

__device__ __forceinline__ void mbar_wait(uint32_t mbar, uint32_t parity) {
    uint32_t done;
    asm volatile(
        "{\n\t.reg .pred p;\n\t"
        "mbarrier.try_wait.parity.acquire.cta.shared::cta.b64 p, [%1], %2;\n\t"
        "selp.b32 %0, 1, 0, p;\n\t}"
        : "=r"(done) : "r"(mbar), "r"(parity) : "memory");
    if (!done) {
        asm volatile(
            "{\n\t.reg .pred P1;\n\t"
            "WAIT_LOOP_%=:\n\t"
            "mbarrier.try_wait.parity.acquire.cta.shared::cta.b64 P1, [%0], %1, 0x989680;\n\t"
            "@P1 bra.uni WAIT_DONE_%=;\n\t"
            "bra.uni WAIT_LOOP_%=;\n\t"
            "WAIT_DONE_%=:\n\t}"
            :: "r"(mbar), "r"(parity) : "memory");
    }
}

__device__ __forceinline__ void bulk_g2s(uint32_t dst, const void* src, uint32_t bytes, uint32_t mbar) {
    asm volatile(
        "cp.async.bulk.shared::cta.global.mbarrier::complete_tx::bytes [%0], [%1], %2, [%3];"
        :: "r"(dst), "l"(src), "r"(bytes), "r"(mbar) : "memory");
}

// ---------------------------------------------------------------------------
// fused prep kernel: X convert (natural+swizzle) | W fold+convert (natural+swizzle)
// ---------------------------------------------------------------------------
#define XBLKS 16384    // 4,194,304 granules (16B out) / 256
#define WBLKS 8192     // (K/128) * (N/16)

__global__ void prep_all(const float* __restrict__ x,
                         const float* __restrict__ W,
                         const float* __restrict__ Bl,
                         const float* __restrict__ Al) {
    const int bx  = blockIdx.x;
    const int tid = threadIdx.x;

    if (bx < XBLKS) {
        // ---- X: fp32 -> fp16, natural layout, swizzle within 128B segment
        const size_t i = (size_t)bx * 256 + tid;     // granule index (8 halves)
        const float4* src = reinterpret_cast<const float4*>(x) + i * 2;
        float4 v0 = src[0], v1 = src[1];
        __half2 h0 = __floats2half2_rn(v0.x, v0.y);
        __half2 h1 = __floats2half2_rn(v0.z, v0.w);
        __half2 h2 = __floats2half2_rn(v1.x, v1.y);
        __half2 h3 = __floats2half2_rn(v1.z, v1.w);
        const size_t   m  = i >> 9;                  // 512 granules per row
        const uint32_t gk = (uint32_t)(i & 511);
        const uint32_t kt = gk >> 3;
        const uint32_t g  = gk & 7;
        const size_t off = m * ROW_BYTES + kt * 128
                         + (((g ^ ((uint32_t)m & 7)) & 7) << 4);
        uint4 p;
        p.x = *reinterpret_cast<uint32_t*>(&h0);
        p.y = *reinterpret_cast<uint32_t*>(&h1);
        p.z = *reinterpret_cast<uint32_t*>(&h2);
        p.w = *reinterpret_cast<uint32_t*>(&h3);
        *reinterpret_cast<uint4*>(reinterpret_cast<char*>(g_Xh) + off) = p;
    } else {
        // ---- W: fold LoRA, convert, natural layout + swizzle
        const int wb = bx - XBLKS;
        const int k0 = (wb & 31) * 128;
        const int n0 = (wb >> 5) * 16;

        __shared__ float As[16 * 128];
        __shared__ float Bs[16 * 16];

        for (int i2 = tid; i2 < 16 * 128; i2 += 256) {
            int r = i2 >> 7, kk = i2 & 127;
            As[i2] = Al[(size_t)r * K_DIM + k0 + kk];
        }
        {
            int nn = tid >> 4, r = tid & 15;
            Bs[nn * 16 + r] = Bl[(size_t)(n0 + nn) * 16 + r];
        }
        __syncthreads();

        const int nn = tid >> 4;
        const int kg = tid & 15;         // 16B granule within 128 k's
        const int n  = n0 + nn;
        const int k  = k0 + kg * 8;
        const float4* wsrc = reinterpret_cast<const float4*>(W + (size_t)n * K_DIM + k);
        float4 w0 = wsrc[0], w1 = wsrc[1];
        float a[8];
        #pragma unroll
        for (int j = 0; j < 8; ++j) a[j] = 0.f;
        const int kl = kg * 8;
        #pragma unroll
        for (int r = 0; r < 16; ++r) {
            float b = Bs[nn * 16 + r];
            #pragma unroll
            for (int j = 0; j < 8; ++j) a[j] += b * As[r * 128 + kl + j];
        }
        __half2 h0 = __floats2half2_rn(w0.x + 2.f * a[0], w0.y + 2.f * a[1]);
        __half2 h1 = __floats2half2_rn(w0.z + 2.f * a[2], w0.w + 2.f * a[3]);
        __half2 h2 = __floats2half2_rn(w1.x + 2.f * a[4], w1.y + 2.f * a[5]);
        __half2 h3 = __floats2half2_rn(w1.z + 2.f * a[6], w1.w + 2.f * a[7]);

        const uint32_t kt = (uint32_t)k >> 6;
        const uint32_t g  = ((uint32_t)k >> 3) & 7;
        const size_t off = (size_t)n * ROW_BYTES + kt * 128
                         + (((g ^ ((uint32_t)n & 7)) & 7) << 4);
        uint4 p;
        p.x = *reinterpret_cast<uint32_t*>(&h0);
        p.y = *reinterpret_cast<uint32_t*>(&h1);
        p.z = *reinterpret_cast<uint32_t*>(&h2);
        p.w = *reinterpret_cast<uint32_t*>(&h3);
        *reinterpret_cast<uint4*>(reinterpret_cast<char*>(g_Wh) + off) = p;
    }
}

// ---------------------------------------------------------------------------
// main GEMM: out[M,N] = Xh @ Wh^T + (bias + 2*db)
// 288 threads: warps 0-7 compute (64x64 over 128x256), warp 8 = producer.
// Producer uses ALL 32 lanes: per stage 128 A-row copies (4/lane) +
// 256 B-row copies (8/lane), 128B each, into the identical stage layout.
// ---------------------------------------------------------------------------
__global__ __launch_bounds__(288, 1) void gemm_f16(
    float* __restrict__ out,
    const float* __restrict__ bias,
    const float* __restrict__ db)
{
    extern __shared__ char smem_raw[];
    const uint32_t sbase = (uint32_t)__cvta_generic_to_shared(smem_raw);
    const int tid  = threadIdx.x;
    const int lane = tid & 31;
    const int warp = tid >> 5;
    const int bN = blockIdx.x;    // 0..15
    const int bM = blockIdx.y;    // 0..63

    // barriers: full[s] at +0..31 ; empty[s] at +32..63
    const uint32_t mb_full0  = sbase;
    const uint32_t mb_empty0 = sbase + 32;

    if (tid == 0) {
        #pragma unroll
        for (int s = 0; s < STAGES; ++s) {
            mbar_init(mb_full0 + 8 * s, 1);
            mbar_init(mb_empty0 + 8 * s, 8);   // 8 compute-warp arrivals
        }
    }
    __syncthreads();

    if (warp == 8) {
        // ---------------- producer warp (all 32 lanes) ----------------
        const char* gA = reinterpret_cast<const char*>(g_Xh)
                       + (size_t)bM * BM * ROW_BYTES;
        const char* gB = reinterpret_cast<const char*>(g_Wh)
                       + (size_t)bN * BN * ROW_BYTES;
        int st = 0, rnd = 0;
        for (int kt = 0; kt < KT; ++kt) {
            const uint32_t full_s = mb_full0 + 8 * st;
            const uint32_t stg = sbase + SMEM_CTRL + st * STAGE_BYTES;
            if (lane == 0) {
                if (rnd > 0) mbar_wait(mb_empty0 + 8 * st, (uint32_t)(rnd - 1) & 1);
                mbar_expect_tx(full_s, STAGE_BYTES);
            }
            __syncwarp();
            const uint32_t kofs = (uint32_t)kt * 128;
            // A: 128 rows, 4 per lane
            #pragma unroll
            for (int j = 0; j < 4; ++j) {
                const int r = lane + j * 32;
                bulk_g2s(stg + r * 128, gA + (size_t)r * ROW_BYTES + kofs, 128, full_s);
            }
            // B: 256 rows, 8 per lane
            #pragma unroll
            for (int j = 0; j < 8; ++j) {
                const int r = lane + j * 32;
                bulk_g2s(stg + A_BLK + r * 128, gB + (size_t)r * ROW_BYTES + kofs, 128, full_s);
            }
            if (++st == STAGES) { st = 0; ++rnd; }
        }
        return;
    }

    // ---------------- compute warps ----------------
    const int warpM = warp & 1;   // 2 warps over M (2*64 = 128)
    const int warpN = warp >> 1;  // 4 warps over N (4*64 = 256)

    float acc[4][8][4];
    #pragma unroll
    for (int i = 0; i < 4; ++i)
        #pragma unroll
        for (int j = 0; j < 8; ++j)
            #pragma unroll
            for (int k = 0; k < 4; ++k) acc[i][j][k] = 0.f;

    // ldsm base byte offsets within a stage; per k16-step s: addr = base ^ (s<<5)
    const uint32_t aoff0 = (uint32_t)(warpM * 64 + (lane & 15)) * 128
                         + ((uint32_t)((lane >> 4) ^ (lane & 7)) << 4);
    const uint32_t boff0 = A_BLK
                         + (uint32_t)(warpN * 64 + (lane & 7) + ((lane >> 4) << 3)) * 128
                         + ((uint32_t)(((lane >> 3) & 1) ^ (lane & 7)) << 4);

    int st_idx = 0;
    uint32_t par = 0;
    for (int kt = 0; kt < KT; ++kt) {
        const uint32_t full_s  = mb_full0  + 8 * st_idx;
        const uint32_t empty_s = mb_empty0 + 8 * st_idx;
        const uint32_t stg = sbase + SMEM_CTRL + st_idx * STAGE_BYTES;

        mbar_wait(full_s, par);     // acquire: stage data visible

        const uint32_t aB = stg + aoff0;
        const uint32_t bB = stg + boff0;

        #pragma unroll
        for (int s = 0; s < 4; ++s) {   // 4 k-steps of 16 per BK=64
            const uint32_t sx = (uint32_t)(s << 5);
            uint32_t af[4][4];
            #pragma unroll
            for (int mi = 0; mi < 4; ++mi)
                ldsm4(af[mi][0], af[mi][1], af[mi][2], af[mi][3],
                      (aB + mi * 2048) ^ sx);
            uint32_t bf[4][4];
            #pragma unroll
            for (int p = 0; p < 4; ++p)
                ldsm4(bf[p][0], bf[p][1], bf[p][2], bf[p][3],
                      (bB + p * 2048) ^ sx);
            #pragma unroll
            for (int mi = 0; mi < 4; ++mi)
                #pragma unroll
                for (int p = 0; p < 4; ++p) {
                    mma_f16(acc[mi][2 * p],     af[mi], bf[p][0], bf[p][1]);
                    mma_f16(acc[mi][2 * p + 1], af[mi], bf[p][2], bf[p][3]);
                }
        }

        if (lane == 0) mbar_arrive(empty_s);
        if (++st_idx == STAGES) { st_idx = 0; par ^= 1; }
    }

    // epilogue: bias folded here (bias + 2*delta_bias), float2 stores
    const int row0 = bM * BM + warpM * 64 + (lane >> 2);
    const int col0 = bN * BN + warpN * 64 + (lane & 3) * 2;
    #pragma unroll
    for (int mi = 0; mi < 4; ++mi) {
        #pragma unroll
        for (int ni = 0; ni < 8; ++ni) {
            int c = col0 + ni * 8;
            float b0 = bias[c]     + 2.0f * db[c];
            float b1 = bias[c + 1] + 2.0f * db[c + 1];
            #pragma unroll
            for (int h = 0; h < 2; ++h) {
                int r = row0 + mi * 16 + h * 8;
                float2 v;
                v.x = acc[mi][ni][2 * h]     + b0;
                v.y = acc[mi][ni][2 * h + 1] + b1;
                *reinterpret_cast<float2*>(out + (size_t)r * N_DIM + c) = v;
            }
        }
    }
}

// ---------------------------------------------------------------------------
extern "C" void kernel_launch(void* const* d_in, const int* in_sizes, int n_in,
                              void* d_out, int out_size) {
    const float* x          = (const float*)d_in[0];
    const float* W          = (const float*)d_in[1];
    const float* bias       = (const float*)d_in[2];
    const float* B_lora     = (const float*)d_in[3];
    const float* A_lora     = (const float*)d_in[4];
    const float* delta_bias = (const float*)d_in[5];
    float* out = (float*)d_out;

    cudaFuncSetAttribute(gemm_f16, cudaFuncAttributeMaxDynamicSharedMemorySize, SMEM_TOTAL);
    cudaFuncSetAttribute(gemm_f16, cudaFuncAttributePreferredSharedMemoryCarveout,
                         cudaSharedmemCarveoutMaxShared);

    prep_all<<<XBLKS + WBLKS, 256>>>(x, W, B_lora, A_lora);
    gemm_f16<<<dim3(N_DIM / BN, M_DIM / BM), 288, SMEM_TOTAL>>>(out, bias, delta_bias);
}

// round 15
// speedup vs baseline: 7.9651x; 7.9651x over previous
#include <cuda_runtime.h>
#include <cuda_fp16.h>
#include <cstdint>
#include <cstddef>

// Problem dims (fixed by the dataset)
#define M_DIM 8192
#define N_DIM 4096
#define K_DIM 4096

#define BM 128
#define BN 256
#define BK 64                                  // 64 halves = 128 B per row
#define KT (K_DIM / BK)                        // 64 iterations per tile
#define A_BLK 16384                            // 128 rows x 128 B
#define B_BLK 32768                            // 256 rows x 128 B
#define STAGE_BYTES (A_BLK + B_BLK)            // 49152
#define STAGES 4
#define SMEM_CTRL 1024
#define SMEM_TOTAL (SMEM_CTRL + STAGES * STAGE_BYTES)   // 197632

// Scratch (allocation-free rule: __device__ globals)
// Packed tile blocks, swizzle pre-applied:
//  g_Xh: block (mt, kt), mt = m>>7, 16KB each: row*128 + ((g^(row&7))<<4)
//  g_Wh: block (nt, kt), nt = n>>8, 32KB each: row*128 + ((g^(row&7))<<4)
__device__ __half g_Xh[(size_t)M_DIM * K_DIM];   // 64 MB
__device__ __half g_Wh[(size_t)N_DIM * K_DIM];   // 32 MB
__device__ float  g_biasp[N_DIM];

// ---------------------------------------------------------------------------
// helpers
// ---------------------------------------------------------------------------
__device__ __forceinline__ void ldsm4(uint32_t& r0, uint32_t& r1, uint32_t& r2, uint32_t& r3,
                                      uint32_t saddr) {
    asm volatile("ldmatrix.sync.aligned.m8n8.x4.shared.b16 {%0,%1,%2,%3}, [%4];\n"
                 : "=r"(r0), "=r"(r1), "=r"(r2), "=r"(r3) : "r"(saddr));
}

__device__ __forceinline__ void mma_f16(float* d, const uint32_t* a, uint32_t b0, uint32_t b1) {
    asm volatile(
        "mma.sync.aligned.m16n8k16.row.col.f32.f16.f16.f32 "
        "{%0,%1,%2,%3},{%4,%5,%6,%7},{%8,%9},{%0,%1,%2,%3};\n"
        : "+f"(d[0]), "+f"(d[1]), "+f"(d[2]), "+f"(d[3])
        : "r"(a[0]), "r"(a[1]), "r"(a[2]), "r"(a[3]), "r"(b0), "r"(b1));
}

__device__ __forceinline__ void mbar_init(uint32_t mbar, uint32_t count) {
    asm volatile("mbarrier.init.shared.b64 [%0], %1;" :: "r"(mbar), "r"(count) : "memory");
}

__device__ __forceinline__ void mbar_expect_tx(uint32_t mbar, uint32_t bytes) {
    asm volatile("mbarrier.arrive.expect_tx.shared.b64 _, [%0], %1;"
                 :: "r"(mbar), "r"(bytes) : "memory");
}

__device__ __forceinline__ void mbar_arrive(uint32_t mbar) {
    asm volatile("mbarrier.arrive.shared.b64 _, [%0];" :: "r"(mbar) : "memory");
}

__device__ __forceinline__ void mbar_wait(uint32_t mbar, uint32_t parity) {
    uint32_t done;
    asm volatile(
        "{\n\t.reg .pred p;\n\t"
        "mbarrier.try_wait.parity.acquire.cta.shared::cta.b64 p, [%1], %2;\n\t"
        "selp.b32 %0, 1, 0, p;\n\t}"
        : "=r"(done) : "r"(mbar), "r"(parity) : "memory");
    if (!done) {
        asm volatile(
            "{\n\t.reg .pred P1;\n\t"
            "WAIT_LOOP_%=:\n\t"
            "mbarrier.try_wait.parity.acquire.cta.shared::cta.b64 P1, [%0], %1, 0x989680;\n\t"
            "@P1 bra.uni WAIT_DONE_%=;\n\t"
            "bra.uni WAIT_LOOP_%=;\n\t"
            "WAIT_DONE_%=:\n\t}"
            :: "r"(mbar), "r"(parity) : "memory");
    }
}

__device__ __forceinline__ void bulk_g2s(uint32_t dst, const void* src, uint32_t bytes, uint32_t mbar) {
    asm volatile(
        "cp.async.bulk.shared::cta.global.mbarrier::complete_tx::bytes [%0], [%1], %2, [%3];"
        :: "r"(dst), "l"(src), "r"(bytes), "r"(mbar) : "memory");
}

// ---------------------------------------------------------------------------
// fused prep kernel: X convert+pack | W fold+convert+pack | bias
// ---------------------------------------------------------------------------
#define XBLKS 4096    // 4,194,304 granules / (256 threads * 4)
#define WBLKS 8192    // (K/128) * (N/16) = 32 * 256

__global__ void prep_all(const float* __restrict__ x,
                         const float* __restrict__ W,
                         const float* __restrict__ B,
                         const float* __restrict__ A,
                         const float* __restrict__ bias,
                         const float* __restrict__ db) {
    const int bx  = blockIdx.x;
    const int tid = threadIdx.x;

    if (bx < XBLKS) {
        // ---- X: fp32 -> fp16, packed blocks. DEST-LINEAR ordering:
        // u = (mt, kt, row, g); consecutive threads -> consecutive g,row
        // => contiguous 128B destination segments (coalesced stores), and
        // per lane-octet 256B contiguous source chunks.
        #pragma unroll
        for (int j = 0; j < 4; ++j) {
            const uint32_t u  = (uint32_t)bx * 1024 + (uint32_t)tid + j * 256;
            const uint32_t g   = u & 7;
            const uint32_t row = (u >> 3) & 127;
            const uint32_t kt  = (u >> 10) & 63;
            const uint32_t mt  = u >> 16;
            const float4* src = reinterpret_cast<const float4*>(
                x + ((size_t)(mt * 128 + row) * K_DIM + kt * 64 + g * 8));
            float4 v0 = src[0], v1 = src[1];
            __half2 h0 = __floats2half2_rn(v0.x, v0.y);
            __half2 h1 = __floats2half2_rn(v0.z, v0.w);
            __half2 h2 = __floats2half2_rn(v1.x, v1.y);
            __half2 h3 = __floats2half2_rn(v1.z, v1.w);
            size_t blk = ((size_t)mt * KT + kt) * (size_t)A_BLK;
            uint32_t off = row * 128 + ((g ^ (row & 7)) << 4);
            uint4 p;
            p.x = *reinterpret_cast<uint32_t*>(&h0);
            p.y = *reinterpret_cast<uint32_t*>(&h1);
            p.z = *reinterpret_cast<uint32_t*>(&h2);
            p.w = *reinterpret_cast<uint32_t*>(&h3);
            *reinterpret_cast<uint4*>(reinterpret_cast<char*>(g_Xh) + blk + off) = p;
        }
    } else if (bx < XBLKS + WBLKS) {
        // ---- W: fold LoRA, convert, pack into 256-row blocks
        const int wb = bx - XBLKS;
        const int k0 = (wb & 31) * 128;
        const int n0 = (wb >> 5) * 16;

        __shared__ float As[16 * 128];
        __shared__ float Bs[16 * 16];

        for (int i2 = tid; i2 < 16 * 128; i2 += 256) {
            int r = i2 >> 7, kk = i2 & 127;
            As[i2] = A[(size_t)r * K_DIM + k0 + kk];
        }
        {
            int nn = tid >> 4, r = tid & 15;
            Bs[nn * 16 + r] = B[(size_t)(n0 + nn) * 16 + r];
        }
        __syncthreads();

        const int nn = tid >> 4;
        const int kg = tid & 15;
        const int n  = n0 + nn;
        const int k  = k0 + kg * 8;
        const float4* wsrc = reinterpret_cast<const float4*>(W + (size_t)n * K_DIM + k);
        float4 w0 = wsrc[0], w1 = wsrc[1];
        float a[8];
        #pragma unroll
        for (int j = 0; j < 8; ++j) a[j] = 0.f;
        const int kl = kg * 8;
        #pragma unroll
        for (int r = 0; r < 16; ++r) {
            float b = Bs[nn * 16 + r];
            #pragma unroll
            for (int j = 0; j < 8; ++j) a[j] += b * As[r * 128 + kl + j];
        }
        __half2 h0 = __floats2half2_rn(w0.x + 2.f * a[0], w0.y + 2.f * a[1]);
        __half2 h1 = __floats2half2_rn(w0.z + 2.f * a[2], w0.w + 2.f * a[3]);
        __half2 h2 = __floats2half2_rn(w1.x + 2.f * a[4], w1.y + 2.f * a[5]);
        __half2 h3 = __floats2half2_rn(w1.z + 2.f * a[6], w1.w + 2.f * a[7]);

        uint32_t nt  = (uint32_t)n >> 8;          // 256-row blocks
        uint32_t row = (uint32_t)n & 255;
        uint32_t kt  = (uint32_t)k >> 6;
        uint32_t g   = ((uint32_t)k >> 3) & 7;
        size_t blk = ((size_t)nt * KT + kt) * (size_t)B_BLK;
        uint32_t off = row * 128 + ((g ^ (row & 7)) << 4);
        uint4 p;
        p.x = *reinterpret_cast<uint32_t*>(&h0);
        p.y = *reinterpret_cast<uint32_t*>(&h1);
        p.z = *reinterpret_cast<uint32_t*>(&h2);
        p.w = *reinterpret_cast<uint32_t*>(&h3);
        *reinterpret_cast<uint4*>(reinterpret_cast<char*>(g_Wh) + blk + off) = p;
    } else {
        // ---- bias' = bias + 2*delta_bias
        for (int i = tid; i < N_DIM; i += 256)
            g_biasp[i] = bias[i] + 2.0f * db[i];
    }
}

// ---------------------------------------------------------------------------
// main GEMM: out[M,N] = Xh @ Wh^T + bias'
// 288 threads: warps 0-7 compute (64x64 tiles over 128x256), warp 8 = producer.
// 4-stage cp.async.bulk + mbarrier rings; no CTA barrier in the loop.
// ---------------------------------------------------------------------------
__global__ __launch_bounds__(288, 1) void gemm_f16(float* __restrict__ out) {
    extern __shared__ float smem_f[];
    const uint32_t sbase = (uint32_t)__cvta_generic_to_shared(smem_f);
    const int tid   = threadIdx.x;
    const int lane  = tid & 31;
    const int warp  = tid >> 5;
    const int bN = blockIdx.x;    // 0..15
    const int bM = blockIdx.y;    // 0..63

    // barriers: full[s] at +0..31 ; empty[s] at +32..63
    const uint32_t mb_full0  = sbase;
    const uint32_t mb_empty0 = sbase + 32;

    if (tid == 0) {
        #pragma unroll
        for (int s = 0; s < STAGES; ++s) {
            mbar_init(mb_full0 + 8 * s, 1);
            mbar_init(mb_empty0 + 8 * s, 8);   // 8 compute-warp arrivals
        }
    }
    __syncthreads();

    const char* gAblk = reinterpret_cast<const char*>(g_Xh) + (size_t)bM * KT * A_BLK;
    const char* gBblk = reinterpret_cast<const char*>(g_Wh) + (size_t)bN * KT * B_BLK;

    if (warp == 8) {
        // ---------------- producer warp ----------------
        if (lane == 0) {
            for (int kt = 0; kt < KT; ++kt) {
                const int s = kt & 3;
                const int r = kt >> 2;
                const uint32_t full_s  = mb_full0 + 8 * s;
                const uint32_t stg = sbase + SMEM_CTRL + s * STAGE_BYTES;
                if (r > 0) mbar_wait(mb_empty0 + 8 * s, (uint32_t)(r - 1) & 1);
                mbar_expect_tx(full_s, STAGE_BYTES);
                bulk_g2s(stg,         gAblk + (size_t)kt * A_BLK, A_BLK, full_s);
                bulk_g2s(stg + A_BLK, gBblk + (size_t)kt * B_BLK, B_BLK, full_s);
            }
        }
        return;
    }

    // ---------------- compute warps ----------------
    const int warpM = warp & 1;   // 2 warps over M (2*64 = 128)
    const int warpN = warp >> 1;  // 4 warps over N (4*64 = 256)

    float acc[4][8][4];
    #pragma unroll
    for (int i = 0; i < 4; ++i)
        #pragma unroll
        for (int j = 0; j < 8; ++j)
            #pragma unroll
            for (int k = 0; k < 4; ++k) acc[i][j][k] = 0.f;

    // ldsm base byte offsets within a stage; per k16-step s: addr = base ^ (s<<5)
    const uint32_t aoff0 = (uint32_t)(warpM * 64 + (lane & 15)) * 128
                         + ((uint32_t)((lane >> 4) ^ (lane & 7)) << 4);
    const uint32_t boff0 = A_BLK
                         + (uint32_t)(warpN * 64 + (lane & 7) + ((lane >> 4) << 3)) * 128
                         + ((uint32_t)(((lane >> 3) & 1) ^ (lane & 7)) << 4);

    for (int kt = 0; kt < KT; ++kt) {
        const int s_idx = kt & 3;
        const uint32_t par = (uint32_t)(kt >> 2) & 1;
        const uint32_t full_s  = mb_full0  + 8 * s_idx;
        const uint32_t empty_s = mb_empty0 + 8 * s_idx;
        const uint32_t stg = sbase + SMEM_CTRL + s_idx * STAGE_BYTES;

        mbar_wait(full_s, par);     // acquire: stage data visible

        const uint32_t aB = stg + aoff0;
        const uint32_t bB = stg + boff0;

        #pragma unroll
        for (int s = 0; s < 4; ++s) {   // 4 k-steps of 16 per BK=64
            const uint32_t sx = (uint32_t)(s << 5);
            uint32_t af[4][4];
            #pragma unroll
            for (int mi = 0; mi < 4; ++mi)
                ldsm4(af[mi][0], af[mi][1], af[mi][2], af[mi][3],
                      (aB + mi * 2048) ^ sx);
            uint32_t bf[4][4];
            #pragma unroll
            for (int p = 0; p < 4; ++p)
                ldsm4(bf[p][0], bf[p][1], bf[p][2], bf[p][3],
                      (bB + p * 2048) ^ sx);
            #pragma unroll
            for (int mi = 0; mi < 4; ++mi)
                #pragma unroll
                for (int p = 0; p < 4; ++p) {
                    mma_f16(acc[mi][2 * p],     af[mi], bf[p][0], bf[p][1]);
                    mma_f16(acc[mi][2 * p + 1], af[mi], bf[p][2], bf[p][3]);
                }
        }

        if (lane == 0) mbar_arrive(empty_s);   // this warp done with stage
    }

    // epilogue: add bias', store float2
    const int row0 = bM * BM + warpM * 64 + (lane >> 2);
    const int col0 = bN * BN + warpN * 64 + (lane & 3) * 2;
    #pragma unroll
    for (int mi = 0; mi < 4; ++mi) {
        #pragma unroll
        for (int ni = 0; ni < 8; ++ni) {
            int c = col0 + ni * 8;
            float b0 = g_biasp[c], b1 = g_biasp[c + 1];
            #pragma unroll
            for (int h = 0; h < 2; ++h) {
                int r = row0 + mi * 16 + h * 8;
                float2 v;
                v.x = acc[mi][ni][2 * h]     + b0;
                v.y = acc[mi][ni][2 * h + 1] + b1;
                *reinterpret_cast<float2*>(out + (size_t)r * N_DIM + c) = v;
            }
        }
    }
}

// ---------------------------------------------------------------------------
extern "C" void kernel_launch(void* const* d_in, const int* in_sizes, int n_in,
                              void* d_out, int out_size) {
    const float* x          = (const float*)d_in[0];
    const float* W          = (const float*)d_in[1];
    const float* bias       = (const float*)d_in[2];
    const float* B_lora     = (const float*)d_in[3];
    const float* A_lora     = (const float*)d_in[4];
    const float* delta_bias = (const float*)d_in[5];
    float* out = (float*)d_out;

    cudaFuncSetAttribute(gemm_f16, cudaFuncAttributeMaxDynamicSharedMemorySize, SMEM_TOTAL);
    cudaFuncSetAttribute(gemm_f16, cudaFuncAttributePreferredSharedMemoryCarveout,
                         cudaSharedmemCarveoutMaxShared);

    prep_all<<<XBLKS + WBLKS + 1, 256>>>(x, W, B_lora, A_lora, bias, delta_bias);
    gemm_f16<<<dim3(N_DIM / BN, M_DIM / BM), 288, SMEM_TOTAL>>>(out);
}